// round 1
// baseline (speedup 1.0000x reference)
#include <cuda_runtime.h>
#include <math.h>

#define CIN 64
#define HW  256
#define HO  128
#define NB  16

// ---------------- device scratch (no allocations allowed) ----------------
__device__ float g_pooled[NB * CIN];
__device__ int   g_selidx[NB * 2];
__device__ float g_selwt [NB * 2];
__device__ float g_bnA[4 * 64];
__device__ float g_bnB[4 * 64];
// transposed weights [e][cin][kh][kw][cout], cout minor
// sizes: e0 64*64*9=36864, e1 102400, e2 200704, e3 331776 -> total 671744
__device__ float g_wT[671744];

// ---------------- global average pool: one block per (b,c) plane ----------------
__global__ void pool_kernel(const float* __restrict__ x) {
    __shared__ float red[256];
    int tid = threadIdx.x;
    const float4* xp = (const float4*)(x + (size_t)blockIdx.x * (HW * HW));
    float s = 0.f;
    for (int i = tid; i < HW * HW / 4; i += 256) {
        float4 v = xp[i];
        s += (v.x + v.y) + (v.z + v.w);
    }
    red[tid] = s;
    __syncthreads();
    for (int off = 128; off > 0; off >>= 1) {
        if (tid < off) red[tid] += red[tid + off];
        __syncthreads();
    }
    if (tid == 0) g_pooled[blockIdx.x] = red[0] * (1.f / (HW * HW));
}

// ---------------- gate: softmax + top-2 renormalized ----------------
__global__ void gate_kernel(const float* __restrict__ gw, const float* __restrict__ gb) {
    int b = threadIdx.x;
    if (b >= NB) return;
    float lg[4];
    for (int e = 0; e < 4; ++e) {
        float s = gb[e];
        for (int c = 0; c < CIN; ++c) s += g_pooled[b * CIN + c] * gw[e * CIN + c];
        lg[e] = s;
    }
    float m = fmaxf(fmaxf(lg[0], lg[1]), fmaxf(lg[2], lg[3]));
    float p[4];
    float Z = 0.f;
    for (int e = 0; e < 4; ++e) { p[e] = expf(lg[e] - m); Z += p[e]; }
    for (int e = 0; e < 4; ++e) p[e] /= Z;
    int i0 = 0;
    for (int e = 1; e < 4; ++e) if (p[e] > p[i0]) i0 = e;     // strict > => lower index wins ties (matches lax.top_k)
    int i1 = -1;
    for (int e = 0; e < 4; ++e) {
        if (e == i0) continue;
        if (i1 < 0 || p[e] > p[i1]) i1 = e;
    }
    float den = p[i0] + p[i1] + 1e-8f;
    g_selidx[b * 2 + 0] = i0; g_selwt[b * 2 + 0] = p[i0] / den;
    g_selidx[b * 2 + 1] = i1; g_selwt[b * 2 + 1] = p[i1] / den;
}

// ---------------- fold conv-bias + BN into y = conv*A + B ----------------
__global__ void bn_kernel(const float* __restrict__ sc, const float* __restrict__ bi,
                          const float* __restrict__ me, const float* __restrict__ va,
                          const float* __restrict__ b0, const float* __restrict__ b1,
                          const float* __restrict__ b2, const float* __restrict__ b3) {
    int t = threadIdx.x;                       // 256 = 4 experts * 64 couts
    const float* bb = (t < 64) ? b0 : (t < 128) ? b1 : (t < 192) ? b2 : b3;
    float inv = sc[t] * rsqrtf(va[t] + 1e-5f);
    g_bnA[t] = inv;
    g_bnB[t] = bb[t & 63] * inv + bi[t] - me[t] * inv;
}

// ---------------- weight transpose: [cout][cin][kidx] -> [cin][kidx][cout] ----------------
__global__ void twk_kernel(const float* __restrict__ w, int off, int KK) {
    int i = blockIdx.x * 256 + threadIdx.x;
    int n = 4096 * KK;                          // 64*64*K*K
    if (i >= n) return;
    int cout = i & 63;
    int row  = i >> 6;                          // cin*KK + kidx
    int cin  = row / KK;
    int kidx = row - cin * KK;
    g_wT[off + i] = w[(cout * 64 + cin) * KK + kidx];
}

// ---------------- expert conv + BN + GELU, packed f32x2 FMA ----------------
// Block: 256 threads = 32(ow) x 8(oh) output tile, all 64 couts per thread
// as 32 packed-f32x2 accumulators. Weights staged to smem in cout-minor pairs.
template <int E, int K, int D, int CHUNK, int WOFF>
__global__ void __launch_bounds__(256, 2)
conv_kernel(const float* __restrict__ x, float* __restrict__ out) {
    const int z = blockIdx.z;                   // b*2 + slot
    if (g_selidx[z] != E) return;

    __shared__ float4 sw4[CHUNK * K * K * 16];  // CHUNK*K*K*64 floats
    float* sw = (float*)sw4;

    const int pad = D * (K - 1) / 2;
    const int tid = threadIdx.x;
    const int ow = blockIdx.x * 32 + (tid & 31);
    const int oh = blockIdx.y * 8 + (tid >> 5);
    const int ohs = 2 * oh - pad;
    const int ows = 2 * ow - pad;

    unsigned rmask = 0, cmask = 0;
#pragma unroll
    for (int k = 0; k < K; ++k) {
        if ((unsigned)(ohs + D * k) < (unsigned)HW) rmask |= 1u << k;
        if ((unsigned)(ows + D * k) < (unsigned)HW) cmask |= 1u << k;
    }

    const float* xb = x + (size_t)(z >> 1) * CIN * HW * HW;

    unsigned long long acc[32];
#pragma unroll
    for (int j = 0; j < 32; ++j) acc[j] = 0ULL;

    const float4* wsrc = (const float4*)(g_wT + WOFF);

    for (int cc = 0; cc < CIN; cc += CHUNK) {
        __syncthreads();
        // contiguous, coalesced, conflict-free staging of this cin-chunk's weights
        for (int i = tid; i < CHUNK * K * K * 16; i += 256)
            sw4[i] = wsrc[cc * (K * K * 16) + i];
        __syncthreads();

#pragma unroll 1
        for (int cl = 0; cl < CHUNK; ++cl) {
            const float* xp = xb + (size_t)(cc + cl) * (HW * HW);
#pragma unroll 1
            for (int kh = 0; kh < K; ++kh) {
                const float* xrow = xp + (ohs + D * kh) * HW + ows;
                const bool rv = (rmask >> kh) & 1;
                const float* wrow = sw + ((cl * K + kh) * K) * 64;
#pragma unroll
                for (int kw = 0; kw < K; ++kw) {
                    float xv = 0.f;
                    if (rv && ((cmask >> kw) & 1)) xv = __ldg(xrow + D * kw);
                    unsigned long long x2;
                    asm("mov.b64 %0, {%1, %1};" : "=l"(x2) : "r"(__float_as_uint(xv)));
                    const ulonglong2* wq = (const ulonglong2*)(wrow + kw * 64);
#pragma unroll
                    for (int j = 0; j < 16; ++j) {
                        ulonglong2 wv = wq[j];   // 16B broadcast LDS: 2 packed cout-pairs
                        asm("fma.rn.f32x2 %0, %1, %2, %0;"
                            : "+l"(acc[2 * j + 0]) : "l"(x2), "l"(wv.x));
                        asm("fma.rn.f32x2 %0, %1, %2, %0;"
                            : "+l"(acc[2 * j + 1]) : "l"(x2), "l"(wv.y));
                    }
                }
            }
        }
    }

    // epilogue: BN fold + exact GELU + gate weight, coalesced stores along ow
    const float wt = g_selwt[z];
    const int b = z >> 1, s = z & 1;
    float* ob = out + ((size_t)b * 128 + s * 64) * (HO * HO) + oh * HO + ow;
#pragma unroll
    for (int p = 0; p < 32; ++p) {
        unsigned u0, u1;
        asm("mov.b64 {%0, %1}, %2;" : "=r"(u0), "=r"(u1) : "l"(acc[p]));
        float v0 = __uint_as_float(u0);
        float v1 = __uint_as_float(u1);
        const int c0 = 2 * p, c1 = 2 * p + 1;
        float y0 = v0 * g_bnA[E * 64 + c0] + g_bnB[E * 64 + c0];
        float y1 = v1 * g_bnA[E * 64 + c1] + g_bnB[E * 64 + c1];
        y0 = 0.5f * y0 * (1.f + erff(y0 * 0.70710678118654752f));
        y1 = 0.5f * y1 * (1.f + erff(y1 * 0.70710678118654752f));
        ob[(size_t)c0 * (HO * HO)] = y0 * wt;
        ob[(size_t)c1 * (HO * HO)] = y1 * wt;
    }
}

// ---------------- launch ----------------
extern "C" void kernel_launch(void* const* d_in, const int* in_sizes, int n_in,
                              void* d_out, int out_size) {
    (void)in_sizes; (void)n_in; (void)out_size;
    const float* x   = (const float*)d_in[0];
    const float* w0  = (const float*)d_in[1];
    const float* b0  = (const float*)d_in[2];
    const float* w1  = (const float*)d_in[3];
    const float* b1  = (const float*)d_in[4];
    const float* w2  = (const float*)d_in[5];
    const float* b2  = (const float*)d_in[6];
    const float* w3  = (const float*)d_in[7];
    const float* b3  = (const float*)d_in[8];
    const float* bns = (const float*)d_in[9];
    const float* bnb = (const float*)d_in[10];
    const float* bnm = (const float*)d_in[11];
    const float* bnv = (const float*)d_in[12];
    const float* gw  = (const float*)d_in[13];
    const float* gb  = (const float*)d_in[14];
    float* out = (float*)d_out;

    pool_kernel<<<NB * CIN, 256>>>(x);
    gate_kernel<<<1, 32>>>(gw, gb);
    bn_kernel<<<1, 256>>>(bns, bnb, bnm, bnv, b0, b1, b2, b3);

    twk_kernel<<<(36864  + 255) / 256, 256>>>(w0, 0,      9);
    twk_kernel<<<(102400 + 255) / 256, 256>>>(w1, 36864,  25);
    twk_kernel<<<(200704 + 255) / 256, 256>>>(w2, 139264, 49);
    twk_kernel<<<(331776 + 255) / 256, 256>>>(w3, 339968, 81);

    dim3 grid(4, 16, NB * 2);   // 128/32 x 128/8 tiles x (b,slot)
    conv_kernel<0, 3, 1, 16, 0     ><<<grid, 256>>>(x, out);
    conv_kernel<1, 5, 2, 4,  36864 ><<<grid, 256>>>(x, out);
    conv_kernel<2, 7, 3, 2,  139264><<<grid, 256>>>(x, out);
    conv_kernel<3, 9, 4, 2,  339968><<<grid, 256>>>(x, out);
}

// round 3
// speedup vs baseline: 1.5954x; 1.5954x over previous
#include <cuda_runtime.h>
#include <math.h>

#define CIN 64
#define HW  256
#define HO  128
#define NB  16

// ---------------- device scratch (no allocations allowed) ----------------
__device__ float g_pooled[NB * CIN];
__device__ int   g_selidx[NB * 2];
__device__ float g_selwt [NB * 2];
__device__ float g_bnA[4 * 64];
__device__ float g_bnB[4 * 64];
// transposed weights [e][cin][kh][kw][cout], cout minor
// sizes: e0 36864, e1 102400, e2 200704, e3 331776 -> total 671744
__device__ float g_wT[671744];

// ---------------- global average pool: one block per (b,c) plane ----------------
__global__ void pool_kernel(const float* __restrict__ x) {
    __shared__ float red[256];
    int tid = threadIdx.x;
    const float4* xp = (const float4*)(x + (size_t)blockIdx.x * (HW * HW));
    float s = 0.f;
    for (int i = tid; i < HW * HW / 4; i += 256) {
        float4 v = xp[i];
        s += (v.x + v.y) + (v.z + v.w);
    }
    red[tid] = s;
    __syncthreads();
    for (int off = 128; off > 0; off >>= 1) {
        if (tid < off) red[tid] += red[tid + off];
        __syncthreads();
    }
    if (tid == 0) g_pooled[blockIdx.x] = red[0] * (1.f / (HW * HW));
}

// ---------------- gate: softmax + top-2 renormalized ----------------
__global__ void gate_kernel(const float* __restrict__ gw, const float* __restrict__ gb) {
    int b = threadIdx.x;
    if (b >= NB) return;
    float lg[4];
    for (int e = 0; e < 4; ++e) {
        float s = gb[e];
        for (int c = 0; c < CIN; ++c) s += g_pooled[b * CIN + c] * gw[e * CIN + c];
        lg[e] = s;
    }
    float m = fmaxf(fmaxf(lg[0], lg[1]), fmaxf(lg[2], lg[3]));
    float p[4];
    float Z = 0.f;
    for (int e = 0; e < 4; ++e) { p[e] = expf(lg[e] - m); Z += p[e]; }
    for (int e = 0; e < 4; ++e) p[e] /= Z;
    int i0 = 0;
    for (int e = 1; e < 4; ++e) if (p[e] > p[i0]) i0 = e;
    int i1 = -1;
    for (int e = 0; e < 4; ++e) {
        if (e == i0) continue;
        if (i1 < 0 || p[e] > p[i1]) i1 = e;
    }
    float den = p[i0] + p[i1] + 1e-8f;
    g_selidx[b * 2 + 0] = i0; g_selwt[b * 2 + 0] = p[i0] / den;
    g_selidx[b * 2 + 1] = i1; g_selwt[b * 2 + 1] = p[i1] / den;
}

// ---------------- fold conv-bias + BN into y = conv*A + B ----------------
__global__ void bn_kernel(const float* __restrict__ sc, const float* __restrict__ bi,
                          const float* __restrict__ me, const float* __restrict__ va,
                          const float* __restrict__ b0, const float* __restrict__ b1,
                          const float* __restrict__ b2, const float* __restrict__ b3) {
    int t = threadIdx.x;
    const float* bb = (t < 64) ? b0 : (t < 128) ? b1 : (t < 192) ? b2 : b3;
    float inv = sc[t] * rsqrtf(va[t] + 1e-5f);
    g_bnA[t] = inv;
    g_bnB[t] = bb[t & 63] * inv + bi[t] - me[t] * inv;
}

// ---------------- weight transpose: [cout][cin][kidx] -> [cin][kidx][cout] ----------------
__global__ void twk_kernel(const float* __restrict__ w, int off, int KK) {
    int i = blockIdx.x * 256 + threadIdx.x;
    int n = 4096 * KK;
    if (i >= n) return;
    int cout = i & 63;
    int row  = i >> 6;
    int cin  = row / KK;
    int kidx = row - cin * KK;
    g_wT[off + i] = w[(cout * 64 + cin) * KK + kidx];
}

// ---------------- merged expert conv + BN + GELU, packed f32x2 FMA ----------------
// Block: 256 threads = 32(ow) x 2(cout-half) x 4(oh-quad). Each thread:
// 32 couts (16 f32x2 pairs) x 4 oh-rows => 64 u64 accumulators (128 regs).
// Each weight LDS.128 (2 cout-pairs) feeds 8 FFMA2 (4 pixels x 2 pairs).
template <int E, int K, int D, int CHUNK, int WOFF>
__device__ __forceinline__ void conv_body(const float* __restrict__ xb,
                                          float* __restrict__ out,
                                          int z, int tid, float4* sw4) {
    const int pad = D * (K - 1) / 2;
    const int owl = tid & 31;
    const int ch  = (tid >> 5) & 1;
    const int ohq = tid >> 6;
    const int ow  = blockIdx.x * 32 + owl;
    const int oh0 = blockIdx.y * 16 + ohq * 4;
    const int ows = 2 * ow - pad;

    int ohs[4];
    unsigned rmask[4];
#pragma unroll
    for (int p = 0; p < 4; ++p) {
        ohs[p] = 2 * (oh0 + p) - pad;
        unsigned m = 0;
#pragma unroll
        for (int k = 0; k < K; ++k)
            if ((unsigned)(ohs[p] + D * k) < (unsigned)HW) m |= 1u << k;
        rmask[p] = m;
    }
    unsigned cmask = 0;
#pragma unroll
    for (int k = 0; k < K; ++k)
        if ((unsigned)(ows + D * k) < (unsigned)HW) cmask |= 1u << k;

    unsigned long long acc[4][16];
#pragma unroll
    for (int p = 0; p < 4; ++p)
#pragma unroll
        for (int j = 0; j < 16; ++j) acc[p][j] = 0ULL;

    float* sw = (float*)sw4;
    const float4* wsrc = (const float4*)(g_wT + WOFF);

    for (int cc = 0; cc < CIN; cc += CHUNK) {
        __syncthreads();
        for (int i = tid; i < CHUNK * K * K * 16; i += 256)
            sw4[i] = wsrc[cc * (K * K * 16) + i];
        __syncthreads();

#pragma unroll 1
        for (int cl = 0; cl < CHUNK; ++cl) {
            const float* xp = xb + (size_t)(cc + cl) * (HW * HW);
#pragma unroll 1
            for (int kh = 0; kh < K; ++kh) {
                const float* wrow = sw + ((cl * K + kh) * K) * 64 + ch * 32;
                const float* xr[4];
                bool rv[4];
#pragma unroll
                for (int p = 0; p < 4; ++p) {
                    xr[p] = xp + (ohs[p] + D * kh) * HW + ows;
                    rv[p] = (rmask[p] >> kh) & 1;
                }
#pragma unroll
                for (int kw = 0; kw < K; ++kw) {
                    const bool cv = (cmask >> kw) & 1;
                    unsigned long long x2[4];
#pragma unroll
                    for (int p = 0; p < 4; ++p) {
                        float v = 0.f;
                        if (rv[p] && cv) v = __ldg(xr[p] + D * kw);
                        asm("mov.b64 %0, {%1, %1};" : "=l"(x2[p]) : "r"(__float_as_uint(v)));
                    }
                    const ulonglong2* wq = (const ulonglong2*)(wrow + kw * 64);
#pragma unroll
                    for (int j = 0; j < 8; ++j) {
                        ulonglong2 wv = wq[j];
#pragma unroll
                        for (int p = 0; p < 4; ++p) {
                            asm("fma.rn.f32x2 %0, %1, %2, %0;"
                                : "+l"(acc[p][2 * j + 0]) : "l"(x2[p]), "l"(wv.x));
                            asm("fma.rn.f32x2 %0, %1, %2, %0;"
                                : "+l"(acc[p][2 * j + 1]) : "l"(x2[p]), "l"(wv.y));
                        }
                    }
                }
            }
        }
    }

    // epilogue: BN fold + exact GELU + gate weight; stores coalesced along ow
    const float wt = g_selwt[z];
    const int b = z >> 1, s = z & 1;
#pragma unroll
    for (int p = 0; p < 4; ++p) {
        float* ob = out + ((size_t)b * 128 + s * 64 + ch * 32) * (HO * HO)
                  + (oh0 + p) * HO + ow;
#pragma unroll
        for (int j = 0; j < 16; ++j) {
            unsigned u0, u1;
            asm("mov.b64 {%0, %1}, %2;" : "=r"(u0), "=r"(u1) : "l"(acc[p][j]));
            float v0 = __uint_as_float(u0);
            float v1 = __uint_as_float(u1);
            const int c0 = ch * 32 + 2 * j, c1 = c0 + 1;
            float y0 = v0 * g_bnA[E * 64 + c0] + g_bnB[E * 64 + c0];
            float y1 = v1 * g_bnA[E * 64 + c1] + g_bnB[E * 64 + c1];
            y0 = 0.5f * y0 * (1.f + erff(y0 * 0.70710678118654752f));
            y1 = 0.5f * y1 * (1.f + erff(y1 * 0.70710678118654752f));
            ob[(size_t)(2 * j) * (HO * HO)]     = y0 * wt;
            ob[(size_t)(2 * j + 1) * (HO * HO)] = y1 * wt;
        }
    }
}

__global__ void __launch_bounds__(256, 1)
conv_all_kernel(const float* __restrict__ x, float* __restrict__ out) {
    __shared__ float4 sw4[2592];   // max: E3 CHUNK=2 -> 2*81*64 floats = 41472 B
    const int z = blockIdx.z;
    const int tid = threadIdx.x;
    const float* xb = x + (size_t)(z >> 1) * CIN * HW * HW;
    const int e = g_selidx[z];
    if (e == 0)      conv_body<0, 3, 1, 16, 0     >(xb, out, z, tid, sw4);
    else if (e == 1) conv_body<1, 5, 2, 4,  36864 >(xb, out, z, tid, sw4);
    else if (e == 2) conv_body<2, 7, 3, 2,  139264>(xb, out, z, tid, sw4);
    else             conv_body<3, 9, 4, 2,  339968>(xb, out, z, tid, sw4);
}

// ---------------- launch ----------------
extern "C" void kernel_launch(void* const* d_in, const int* in_sizes, int n_in,
                              void* d_out, int out_size) {
    (void)in_sizes; (void)n_in; (void)out_size;
    const float* x   = (const float*)d_in[0];
    const float* w0  = (const float*)d_in[1];
    const float* b0  = (const float*)d_in[2];
    const float* w1  = (const float*)d_in[3];
    const float* b1  = (const float*)d_in[4];
    const float* w2  = (const float*)d_in[5];
    const float* b2  = (const float*)d_in[6];
    const float* w3  = (const float*)d_in[7];
    const float* b3  = (const float*)d_in[8];
    const float* bns = (const float*)d_in[9];
    const float* bnb = (const float*)d_in[10];
    const float* bnm = (const float*)d_in[11];
    const float* bnv = (const float*)d_in[12];
    const float* gw  = (const float*)d_in[13];
    const float* gb  = (const float*)d_in[14];
    float* out = (float*)d_out;

    pool_kernel<<<NB * CIN, 256>>>(x);
    gate_kernel<<<1, 32>>>(gw, gb);
    bn_kernel<<<1, 256>>>(bns, bnb, bnm, bnv, b0, b1, b2, b3);

    twk_kernel<<<(36864  + 255) / 256, 256>>>(w0, 0,      9);
    twk_kernel<<<(102400 + 255) / 256, 256>>>(w1, 36864,  25);
    twk_kernel<<<(200704 + 255) / 256, 256>>>(w2, 139264, 49);
    twk_kernel<<<(331776 + 255) / 256, 256>>>(w3, 339968, 81);

    dim3 grid(4, 8, NB * 2);   // 128/32 ow-tiles x 128/16 oh-tiles x (b,slot)
    conv_all_kernel<<<grid, 256>>>(x, out);
}

// round 5
// speedup vs baseline: 1.6342x; 1.0243x over previous
#include <cuda_runtime.h>
#include <math.h>

#define CIN 64
#define HW  256
#define HO  128
#define NB  16

// ---------------- device scratch (no allocations allowed) ----------------
__device__ float g_pooled[NB * CIN];
__device__ int   g_selidx[NB * 2];
__device__ float g_selwt [NB * 2];
__device__ int   g_sched [NB * 2];   // block order: heavy experts first
__device__ float g_bnA[4 * 64];
__device__ float g_bnB[4 * 64];
// transposed weights [e][cin][kh][kw][cout], cout minor
// sizes: e0 36864, e1 102400, e2 200704, e3 331776 -> total 671744
__device__ float g_wT[671744];

// ---------------- global average pool: one block per (b,c) plane ----------------
__global__ void pool_kernel(const float* __restrict__ x) {
    __shared__ float red[256];
    int tid = threadIdx.x;
    const float4* xp = (const float4*)(x + (size_t)blockIdx.x * (HW * HW));
    float s = 0.f;
    for (int i = tid; i < HW * HW / 4; i += 256) {
        float4 v = xp[i];
        s += (v.x + v.y) + (v.z + v.w);
    }
    red[tid] = s;
    __syncthreads();
    for (int off = 128; off > 0; off >>= 1) {
        if (tid < off) red[tid] += red[tid + off];
        __syncthreads();
    }
    if (tid == 0) g_pooled[blockIdx.x] = red[0] * (1.f / (HW * HW));
}

// ---------------- gate: softmax + top-2 renormalized + schedule ----------------
__global__ void gate_kernel(const float* __restrict__ gw, const float* __restrict__ gb) {
    __shared__ int s_idx[NB * 2];
    int b = threadIdx.x;
    if (b < NB) {
        float lg[4];
        for (int e = 0; e < 4; ++e) {
            float s = gb[e];
            for (int c = 0; c < CIN; ++c) s += g_pooled[b * CIN + c] * gw[e * CIN + c];
            lg[e] = s;
        }
        float m = fmaxf(fmaxf(lg[0], lg[1]), fmaxf(lg[2], lg[3]));
        float p[4];
        float Z = 0.f;
        for (int e = 0; e < 4; ++e) { p[e] = expf(lg[e] - m); Z += p[e]; }
        for (int e = 0; e < 4; ++e) p[e] /= Z;
        int i0 = 0;
        for (int e = 1; e < 4; ++e) if (p[e] > p[i0]) i0 = e;
        int i1 = -1;
        for (int e = 0; e < 4; ++e) {
            if (e == i0) continue;
            if (i1 < 0 || p[e] > p[i1]) i1 = e;
        }
        float den = p[i0] + p[i1] + 1e-8f;
        g_selidx[b * 2 + 0] = i0; g_selwt[b * 2 + 0] = p[i0] / den;
        g_selidx[b * 2 + 1] = i1; g_selwt[b * 2 + 1] = p[i1] / den;
        s_idx[b * 2 + 0] = i0;
        s_idx[b * 2 + 1] = i1;
    }
    __syncthreads();
    if (threadIdx.x == 0) {
        // stable counting sort, heaviest expert (largest K) first
        int n = 0;
        for (int e = 3; e >= 0; --e)
            for (int z = 0; z < NB * 2; ++z)
                if (s_idx[z] == e) g_sched[n++] = z;
    }
}

// ---------------- fold conv-bias + BN into y = conv*A + B ----------------
__global__ void bn_kernel(const float* __restrict__ sc, const float* __restrict__ bi,
                          const float* __restrict__ me, const float* __restrict__ va,
                          const float* __restrict__ b0, const float* __restrict__ b1,
                          const float* __restrict__ b2, const float* __restrict__ b3) {
    int t = threadIdx.x;
    const float* bb = (t < 64) ? b0 : (t < 128) ? b1 : (t < 192) ? b2 : b3;
    float inv = sc[t] * rsqrtf(va[t] + 1e-5f);
    g_bnA[t] = inv;
    g_bnB[t] = bb[t & 63] * inv + bi[t] - me[t] * inv;
}

// ---------------- weight transpose: [cout][cin][kidx] -> [cin][kidx][cout] ----------------
__device__ __forceinline__ void twk_one(const float* __restrict__ w, int off, int KK, int i) {
    int cout = i & 63;
    int row  = i >> 6;
    int cin  = row / KK;
    int kidx = row - cin * KK;
    g_wT[off + i] = w[(cout * 64 + cin) * KK + kidx];
}

// experts 0+1 in one launch (36864 + 102400 = 139264 elements)
__global__ void twkA_kernel(const float* __restrict__ w0, const float* __restrict__ w1) {
    int i = blockIdx.x * 256 + threadIdx.x;
    if (i < 36864)       twk_one(w0, 0, 9, i);
    else if (i < 139264) twk_one(w1, 36864, 25, i - 36864);
}

// experts 2+3 in one launch (200704 + 331776 = 532480 elements)
__global__ void twkB_kernel(const float* __restrict__ w2, const float* __restrict__ w3) {
    int i = blockIdx.x * 256 + threadIdx.x;
    if (i < 200704)      twk_one(w2, 139264, 49, i);
    else if (i < 532480) twk_one(w3, 339968, 81, i - 200704);
}

// ---------------- merged expert conv + BN + GELU, packed f32x2 FMA ----------------
// Block: 256 threads = 32(ow) x 2(cout-half) x 4(oh-quad). Each thread:
// 32 couts (16 f32x2 pairs) x 4 oh-rows => 64 u64 accumulators (128 regs).
// Each weight LDS.128 (2 cout-pairs) feeds 8 FFMA2 (4 pixels x 2 pairs).
// x loads for a full kh-row are batched before the FMA loops (MLP ~ 4K).
template <int E, int K, int D, int CHUNK, int WOFF>
__device__ __forceinline__ void conv_body(const float* __restrict__ xb,
                                          float* __restrict__ out,
                                          int z, int tid, float4* sw4) {
    const int pad = D * (K - 1) / 2;
    const int owl = tid & 31;
    const int ch  = (tid >> 5) & 1;
    const int ohq = tid >> 6;
    const int ow  = blockIdx.x * 32 + owl;
    const int oh0 = blockIdx.y * 16 + ohq * 4;
    const int ows = 2 * ow - pad;

    int ohs[4];
    unsigned rmask[4];
#pragma unroll
    for (int p = 0; p < 4; ++p) {
        ohs[p] = 2 * (oh0 + p) - pad;
        unsigned m = 0;
#pragma unroll
        for (int k = 0; k < K; ++k)
            if ((unsigned)(ohs[p] + D * k) < (unsigned)HW) m |= 1u << k;
        rmask[p] = m;
    }
    unsigned cmask = 0;
#pragma unroll
    for (int k = 0; k < K; ++k)
        if ((unsigned)(ows + D * k) < (unsigned)HW) cmask |= 1u << k;

    unsigned long long acc[4][16];
#pragma unroll
    for (int p = 0; p < 4; ++p)
#pragma unroll
        for (int j = 0; j < 16; ++j) acc[p][j] = 0ULL;

    float* sw = (float*)sw4;
    const float4* wsrc = (const float4*)(g_wT + WOFF);

    for (int cc = 0; cc < CIN; cc += CHUNK) {
        __syncthreads();
        for (int i = tid; i < CHUNK * K * K * 16; i += 256)
            sw4[i] = wsrc[cc * (K * K * 16) + i];
        __syncthreads();

#pragma unroll 1
        for (int cl = 0; cl < CHUNK; ++cl) {
            const float* xp = xb + (size_t)(cc + cl) * (HW * HW);
#pragma unroll 1
            for (int kh = 0; kh < K; ++kh) {
                const float* wrow = sw + ((cl * K + kh) * K) * 64 + ch * 32;
                // ---- batched x loads for the whole kh row (high MLP) ----
                float xv[4 * K];
#pragma unroll
                for (int p = 0; p < 4; ++p) {
                    const float* xr = xp + (ohs[p] + D * kh) * HW + ows;
                    const bool rv = (rmask[p] >> kh) & 1;
#pragma unroll
                    for (int kw = 0; kw < K; ++kw) {
                        float v = 0.f;
                        if (rv && ((cmask >> kw) & 1)) v = __ldg(xr + D * kw);
                        xv[p * K + kw] = v;
                    }
                }
                // ---- pure LDS + FFMA2 ----
#pragma unroll
                for (int kw = 0; kw < K; ++kw) {
                    unsigned long long x2[4];
#pragma unroll
                    for (int p = 0; p < 4; ++p)
                        asm("mov.b64 %0, {%1, %1};" : "=l"(x2[p])
                            : "r"(__float_as_uint(xv[p * K + kw])));
                    const ulonglong2* wq = (const ulonglong2*)(wrow + kw * 64);
#pragma unroll
                    for (int j = 0; j < 8; ++j) {
                        ulonglong2 wv = wq[j];
#pragma unroll
                        for (int p = 0; p < 4; ++p) {
                            asm("fma.rn.f32x2 %0, %1, %2, %0;"
                                : "+l"(acc[p][2 * j + 0]) : "l"(x2[p]), "l"(wv.x));
                            asm("fma.rn.f32x2 %0, %1, %2, %0;"
                                : "+l"(acc[p][2 * j + 1]) : "l"(x2[p]), "l"(wv.y));
                        }
                    }
                }
            }
        }
    }

    // epilogue: BN fold + exact GELU + gate weight; stores coalesced along ow
    const float wt = g_selwt[z];
    const int b = z >> 1, s = z & 1;
#pragma unroll
    for (int p = 0; p < 4; ++p) {
        float* ob = out + ((size_t)b * 128 + s * 64 + ch * 32) * (HO * HO)
                  + (oh0 + p) * HO + ow;
#pragma unroll
        for (int j = 0; j < 16; ++j) {
            unsigned u0, u1;
            asm("mov.b64 {%0, %1}, %2;" : "=r"(u0), "=r"(u1) : "l"(acc[p][j]));
            float v0 = __uint_as_float(u0);
            float v1 = __uint_as_float(u1);
            const int c0 = ch * 32 + 2 * j, c1 = c0 + 1;
            float y0 = v0 * g_bnA[E * 64 + c0] + g_bnB[E * 64 + c0];
            float y1 = v1 * g_bnA[E * 64 + c1] + g_bnB[E * 64 + c1];
            y0 = 0.5f * y0 * (1.f + erff(y0 * 0.70710678118654752f));
            y1 = 0.5f * y1 * (1.f + erff(y1 * 0.70710678118654752f));
            ob[(size_t)(2 * j) * (HO * HO)]     = y0 * wt;
            ob[(size_t)(2 * j + 1) * (HO * HO)] = y1 * wt;
        }
    }
}

__global__ void __launch_bounds__(256, 1)
conv_all_kernel(const float* __restrict__ x, float* __restrict__ out) {
    __shared__ float4 sw4[2592];   // max: E3 CHUNK=2 -> 2*81*64 floats = 41472 B
    const int z = g_sched[blockIdx.z];          // heavy-first schedule
    const int tid = threadIdx.x;
    const float* xb = x + (size_t)(z >> 1) * CIN * HW * HW;
    const int e = g_selidx[z];
    if (e == 0)      conv_body<0, 3, 1, 16, 0     >(xb, out, z, tid, sw4);
    else if (e == 1) conv_body<1, 5, 2, 4,  36864 >(xb, out, z, tid, sw4);
    else if (e == 2) conv_body<2, 7, 3, 2,  139264>(xb, out, z, tid, sw4);
    else             conv_body<3, 9, 4, 2,  339968>(xb, out, z, tid, sw4);
}

// ---------------- launch (exactly 6 launches so ncu -s 5 -c 1 lands on conv) ----------------
extern "C" void kernel_launch(void* const* d_in, const int* in_sizes, int n_in,
                              void* d_out, int out_size) {
    (void)in_sizes; (void)n_in; (void)out_size;
    const float* x   = (const float*)d_in[0];
    const float* w0  = (const float*)d_in[1];
    const float* b0  = (const float*)d_in[2];
    const float* w1  = (const float*)d_in[3];
    const float* b1  = (const float*)d_in[4];
    const float* w2  = (const float*)d_in[5];
    const float* b2  = (const float*)d_in[6];
    const float* w3  = (const float*)d_in[7];
    const float* b3  = (const float*)d_in[8];
    const float* bns = (const float*)d_in[9];
    const float* bnb = (const float*)d_in[10];
    const float* bnm = (const float*)d_in[11];
    const float* bnv = (const float*)d_in[12];
    const float* gw  = (const float*)d_in[13];
    const float* gb  = (const float*)d_in[14];
    float* out = (float*)d_out;

    pool_kernel<<<NB * CIN, 256>>>(x);                       // 1
    gate_kernel<<<1, 32>>>(gw, gb);                          // 2
    bn_kernel<<<1, 256>>>(bns, bnb, bnm, bnv, b0, b1, b2, b3); // 3
    twkA_kernel<<<(139264 + 255) / 256, 256>>>(w0, w1);      // 4
    twkB_kernel<<<(532480 + 255) / 256, 256>>>(w2, w3);      // 5

    dim3 grid(4, 8, NB * 2);   // 128/32 ow-tiles x 128/16 oh-tiles x (b,slot)
    conv_all_kernel<<<grid, 256>>>(x, out);                  // 6
}

// round 6
// speedup vs baseline: 1.6343x; 1.0001x over previous
#include <cuda_runtime.h>
#include <math.h>

#define CIN 64
#define HW  256
#define HO  128
#define NB  16

// ---------------- device scratch (no allocations allowed) ----------------
__device__ float g_pooled[NB * CIN];
__device__ int   g_selidx[NB * 2];
__device__ float g_selwt [NB * 2];
__device__ int   g_sched [NB * 2];   // block order: heavy experts first
__device__ float g_bnA[4 * 64];
__device__ float g_bnB[4 * 64];
// transposed weights [e][cin][kh][kw][cout], cout minor
// sizes: e0 36864, e1 102400, e2 200704, e3 331776 -> total 671744
__device__ float g_wT[671744];

// ---------------- launch #1: global average pool, one block per (b,c) plane ----
__global__ void pool_kernel(const float* __restrict__ x) {
    __shared__ float red[256];
    int tid = threadIdx.x;
    const float4* xp = (const float4*)(x + (size_t)blockIdx.x * (HW * HW));
    float s = 0.f;
    for (int i = tid; i < HW * HW / 4; i += 256) {
        float4 v = xp[i];
        s += (v.x + v.y) + (v.z + v.w);
    }
    red[tid] = s;
    __syncthreads();
    for (int off = 128; off > 0; off >>= 1) {
        if (tid < off) red[tid] += red[tid + off];
        __syncthreads();
    }
    if (tid == 0) g_pooled[blockIdx.x] = red[0] * (1.f / (HW * HW));
}

// ---------------- launch #2: ALL weight transposes in one kernel ----------------
__device__ __forceinline__ void twk_one(const float* __restrict__ w, int off, int KK, int i) {
    int cout = i & 63;
    int row  = i >> 6;
    int cin  = row / KK;
    int kidx = row - cin * KK;
    g_wT[off + i] = w[(cout * 64 + cin) * KK + kidx];
}

__global__ void twk_all_kernel(const float* __restrict__ w0, const float* __restrict__ w1,
                               const float* __restrict__ w2, const float* __restrict__ w3) {
    int i = blockIdx.x * 256 + threadIdx.x;
    if (i < 36864)       twk_one(w0, 0,      9,  i);
    else if (i < 139264) twk_one(w1, 36864,  25, i - 36864);
    else if (i < 339968) twk_one(w2, 139264, 49, i - 139264);
    else if (i < 671744) twk_one(w3, 339968, 81, i - 339968);
}

// ---------------- launch #3: gate (softmax + top-2 + schedule) AND bn fold ------
__global__ void gatebn_kernel(const float* __restrict__ gw, const float* __restrict__ gb,
                              const float* __restrict__ sc, const float* __restrict__ bi,
                              const float* __restrict__ me, const float* __restrict__ va,
                              const float* __restrict__ b0, const float* __restrict__ b1,
                              const float* __restrict__ b2, const float* __restrict__ b3) {
    __shared__ int s_idx[NB * 2];
    int t = threadIdx.x;

    // BN fold: y = conv*A + B  (256 threads = 4 experts x 64 couts)
    {
        const float* bb = (t < 64) ? b0 : (t < 128) ? b1 : (t < 192) ? b2 : b3;
        float inv = sc[t] * rsqrtf(va[t] + 1e-5f);
        g_bnA[t] = inv;
        g_bnB[t] = bb[t & 63] * inv + bi[t] - me[t] * inv;
    }

    // Gate (threads 0..15, one per batch)
    if (t < NB) {
        int b = t;
        float lg[4];
        for (int e = 0; e < 4; ++e) {
            float s = gb[e];
            for (int c = 0; c < CIN; ++c) s += g_pooled[b * CIN + c] * gw[e * CIN + c];
            lg[e] = s;
        }
        float m = fmaxf(fmaxf(lg[0], lg[1]), fmaxf(lg[2], lg[3]));
        float p[4];
        float Z = 0.f;
        for (int e = 0; e < 4; ++e) { p[e] = expf(lg[e] - m); Z += p[e]; }
        for (int e = 0; e < 4; ++e) p[e] /= Z;
        int i0 = 0;
        for (int e = 1; e < 4; ++e) if (p[e] > p[i0]) i0 = e;   // strict >, lower idx wins ties
        int i1 = -1;
        for (int e = 0; e < 4; ++e) {
            if (e == i0) continue;
            if (i1 < 0 || p[e] > p[i1]) i1 = e;
        }
        float den = p[i0] + p[i1] + 1e-8f;
        g_selidx[b * 2 + 0] = i0; g_selwt[b * 2 + 0] = p[i0] / den;
        g_selidx[b * 2 + 1] = i1; g_selwt[b * 2 + 1] = p[i1] / den;
        s_idx[b * 2 + 0] = i0;
        s_idx[b * 2 + 1] = i1;
    }
    __syncthreads();
    if (t == 0) {
        // stable counting sort, heaviest expert (largest K) first
        int n = 0;
        for (int e = 3; e >= 0; --e)
            for (int z = 0; z < NB * 2; ++z)
                if (s_idx[z] == e) g_sched[n++] = z;
    }
}

// ---------------- launch #4: merged expert conv + BN + GELU, packed f32x2 FMA ---
// Block: 256 threads = 32(ow) x 2(cout-half) x 4(oh-quad). Each thread:
// 32 couts (16 f32x2 pairs) x 4 oh-rows => 64 u64 accumulators (128 regs).
// Each weight LDS.128 (2 cout-pairs) feeds 8 FFMA2 (4 pixels x 2 pairs).
// x loads for a full kh-row are batched before the FMA loops (MLP ~ 4K).
template <int E, int K, int D, int CHUNK, int WOFF>
__device__ __forceinline__ void conv_body(const float* __restrict__ xb,
                                          float* __restrict__ out,
                                          int z, int tid, float4* sw4) {
    const int pad = D * (K - 1) / 2;
    const int owl = tid & 31;
    const int ch  = (tid >> 5) & 1;
    const int ohq = tid >> 6;
    const int ow  = blockIdx.x * 32 + owl;
    const int oh0 = blockIdx.y * 16 + ohq * 4;
    const int ows = 2 * ow - pad;

    int ohs[4];
    unsigned rmask[4];
#pragma unroll
    for (int p = 0; p < 4; ++p) {
        ohs[p] = 2 * (oh0 + p) - pad;
        unsigned m = 0;
#pragma unroll
        for (int k = 0; k < K; ++k)
            if ((unsigned)(ohs[p] + D * k) < (unsigned)HW) m |= 1u << k;
        rmask[p] = m;
    }
    unsigned cmask = 0;
#pragma unroll
    for (int k = 0; k < K; ++k)
        if ((unsigned)(ows + D * k) < (unsigned)HW) cmask |= 1u << k;

    unsigned long long acc[4][16];
#pragma unroll
    for (int p = 0; p < 4; ++p)
#pragma unroll
        for (int j = 0; j < 16; ++j) acc[p][j] = 0ULL;

    float* sw = (float*)sw4;
    const float4* wsrc = (const float4*)(g_wT + WOFF);

    for (int cc = 0; cc < CIN; cc += CHUNK) {
        __syncthreads();
        for (int i = tid; i < CHUNK * K * K * 16; i += 256)
            sw4[i] = wsrc[cc * (K * K * 16) + i];
        __syncthreads();

#pragma unroll 1
        for (int cl = 0; cl < CHUNK; ++cl) {
            const float* xp = xb + (size_t)(cc + cl) * (HW * HW);
#pragma unroll 1
            for (int kh = 0; kh < K; ++kh) {
                const float* wrow = sw + ((cl * K + kh) * K) * 64 + ch * 32;
                // ---- batched x loads for the whole kh row (high MLP) ----
                float xv[4 * K];
#pragma unroll
                for (int p = 0; p < 4; ++p) {
                    const float* xr = xp + (ohs[p] + D * kh) * HW + ows;
                    const bool rv = (rmask[p] >> kh) & 1;
#pragma unroll
                    for (int kw = 0; kw < K; ++kw) {
                        float v = 0.f;
                        if (rv && ((cmask >> kw) & 1)) v = __ldg(xr + D * kw);
                        xv[p * K + kw] = v;
                    }
                }
                // ---- pure LDS + FFMA2 ----
#pragma unroll
                for (int kw = 0; kw < K; ++kw) {
                    unsigned long long x2[4];
#pragma unroll
                    for (int p = 0; p < 4; ++p)
                        asm("mov.b64 %0, {%1, %1};" : "=l"(x2[p])
                            : "r"(__float_as_uint(xv[p * K + kw])));
                    const ulonglong2* wq = (const ulonglong2*)(wrow + kw * 64);
#pragma unroll
                    for (int j = 0; j < 8; ++j) {
                        ulonglong2 wv = wq[j];
#pragma unroll
                        for (int p = 0; p < 4; ++p) {
                            asm("fma.rn.f32x2 %0, %1, %2, %0;"
                                : "+l"(acc[p][2 * j + 0]) : "l"(x2[p]), "l"(wv.x));
                            asm("fma.rn.f32x2 %0, %1, %2, %0;"
                                : "+l"(acc[p][2 * j + 1]) : "l"(x2[p]), "l"(wv.y));
                        }
                    }
                }
            }
        }
    }

    // epilogue: BN fold + exact GELU + gate weight; stores coalesced along ow
    const float wt = g_selwt[z];
    const int b = z >> 1, s = z & 1;
#pragma unroll
    for (int p = 0; p < 4; ++p) {
        float* ob = out + ((size_t)b * 128 + s * 64 + ch * 32) * (HO * HO)
                  + (oh0 + p) * HO + ow;
#pragma unroll
        for (int j = 0; j < 16; ++j) {
            unsigned u0, u1;
            asm("mov.b64 {%0, %1}, %2;" : "=r"(u0), "=r"(u1) : "l"(acc[p][j]));
            float v0 = __uint_as_float(u0);
            float v1 = __uint_as_float(u1);
            const int c0 = ch * 32 + 2 * j, c1 = c0 + 1;
            float y0 = v0 * g_bnA[E * 64 + c0] + g_bnB[E * 64 + c0];
            float y1 = v1 * g_bnA[E * 64 + c1] + g_bnB[E * 64 + c1];
            y0 = 0.5f * y0 * (1.f + erff(y0 * 0.70710678118654752f));
            y1 = 0.5f * y1 * (1.f + erff(y1 * 0.70710678118654752f));
            ob[(size_t)(2 * j) * (HO * HO)]     = y0 * wt;
            ob[(size_t)(2 * j + 1) * (HO * HO)] = y1 * wt;
        }
    }
}

__global__ void __launch_bounds__(256, 1)
conv_all_kernel(const float* __restrict__ x, float* __restrict__ out) {
    __shared__ float4 sw4[2592];   // max: E3 CHUNK=2 -> 2*81*64 floats = 41472 B
    const int z = g_sched[blockIdx.z];          // heavy-first schedule
    const int tid = threadIdx.x;
    const float* xb = x + (size_t)(z >> 1) * CIN * HW * HW;
    const int e = g_selidx[z];
    if (e == 0)      conv_body<0, 3, 1, 16, 0     >(xb, out, z, tid, sw4);
    else if (e == 1) conv_body<1, 5, 2, 4,  36864 >(xb, out, z, tid, sw4);
    else if (e == 2) conv_body<2, 7, 3, 2,  139264>(xb, out, z, tid, sw4);
    else             conv_body<3, 9, 4, 2,  339968>(xb, out, z, tid, sw4);
}

// ---------------- launch: exactly 4 launches, conv is #4 (ncu capture slot) -----
extern "C" void kernel_launch(void* const* d_in, const int* in_sizes, int n_in,
                              void* d_out, int out_size) {
    (void)in_sizes; (void)n_in; (void)out_size;
    const float* x   = (const float*)d_in[0];
    const float* w0  = (const float*)d_in[1];
    const float* b0  = (const float*)d_in[2];
    const float* w1  = (const float*)d_in[3];
    const float* b1  = (const float*)d_in[4];
    const float* w2  = (const float*)d_in[5];
    const float* b2  = (const float*)d_in[6];
    const float* w3  = (const float*)d_in[7];
    const float* b3  = (const float*)d_in[8];
    const float* bns = (const float*)d_in[9];
    const float* bnb = (const float*)d_in[10];
    const float* bnm = (const float*)d_in[11];
    const float* bnv = (const float*)d_in[12];
    const float* gw  = (const float*)d_in[13];
    const float* gb  = (const float*)d_in[14];
    float* out = (float*)d_out;

    pool_kernel<<<NB * CIN, 256>>>(x);                               // #1
    twk_all_kernel<<<(671744 + 255) / 256, 256>>>(w0, w1, w2, w3);   // #2
    gatebn_kernel<<<1, 256>>>(gw, gb, bns, bnb, bnm, bnv,
                              b0, b1, b2, b3);                       // #3
    dim3 grid(4, 8, NB * 2);   // 128/32 ow-tiles x 128/16 oh-tiles x (b,slot)
    conv_all_kernel<<<grid, 256>>>(x, out);                          // #4
}

// round 7
// speedup vs baseline: 1.6521x; 1.0109x over previous
#include <cuda_runtime.h>
#include <math.h>

#define CIN 64
#define HW  256
#define HO  128
#define NB  16

// ---------------- device scratch (no allocations allowed) ----------------
__device__ float g_pooled[NB * CIN];
__device__ int   g_selidx[NB * 2];
__device__ float g_selwt [NB * 2];
__device__ int   g_sched [NB * 2];   // block order: heavy experts first
__device__ float g_bnA[4 * 64];
__device__ float g_bnB[4 * 64];
// transposed weights [e][cin][kh][kw][cout], cout minor
// sizes: e0 36864, e1 102400, e2 200704, e3 331776 -> total 671744
__device__ float g_wT[671744];

// ---------------- launch #1: global average pool, one block per (b,c) plane ----
__global__ void pool_kernel(const float* __restrict__ x) {
    __shared__ float red[256];
    int tid = threadIdx.x;
    const float4* xp = (const float4*)(x + (size_t)blockIdx.x * (HW * HW));
    float s = 0.f;
    for (int i = tid; i < HW * HW / 4; i += 256) {
        float4 v = xp[i];
        s += (v.x + v.y) + (v.z + v.w);
    }
    red[tid] = s;
    __syncthreads();
    for (int off = 128; off > 0; off >>= 1) {
        if (tid < off) red[tid] += red[tid + off];
        __syncthreads();
    }
    if (tid == 0) g_pooled[blockIdx.x] = red[0] * (1.f / (HW * HW));
}

// ---------------- launch #2: ALL weight transposes in one kernel ----------------
__device__ __forceinline__ void twk_one(const float* __restrict__ w, int off, int KK, int i) {
    int cout = i & 63;
    int row  = i >> 6;
    int cin  = row / KK;
    int kidx = row - cin * KK;
    g_wT[off + i] = w[(cout * 64 + cin) * KK + kidx];
}

__global__ void twk_all_kernel(const float* __restrict__ w0, const float* __restrict__ w1,
                               const float* __restrict__ w2, const float* __restrict__ w3) {
    int i = blockIdx.x * 256 + threadIdx.x;
    if (i < 36864)       twk_one(w0, 0,      9,  i);
    else if (i < 139264) twk_one(w1, 36864,  25, i - 36864);
    else if (i < 339968) twk_one(w2, 139264, 49, i - 139264);
    else if (i < 671744) twk_one(w3, 339968, 81, i - 339968);
}

// ---------------- launch #3: gate (softmax + top-2 + schedule) AND bn fold ------
__global__ void gatebn_kernel(const float* __restrict__ gw, const float* __restrict__ gb,
                              const float* __restrict__ sc, const float* __restrict__ bi,
                              const float* __restrict__ me, const float* __restrict__ va,
                              const float* __restrict__ b0, const float* __restrict__ b1,
                              const float* __restrict__ b2, const float* __restrict__ b3) {
    __shared__ int s_idx[NB * 2];
    int t = threadIdx.x;

    // BN fold: y = conv*A + B  (256 threads = 4 experts x 64 couts)
    {
        const float* bb = (t < 64) ? b0 : (t < 128) ? b1 : (t < 192) ? b2 : b3;
        float inv = sc[t] * rsqrtf(va[t] + 1e-5f);
        g_bnA[t] = inv;
        g_bnB[t] = bb[t & 63] * inv + bi[t] - me[t] * inv;
    }

    // Gate (threads 0..15, one per batch)
    if (t < NB) {
        int b = t;
        float lg[4];
        for (int e = 0; e < 4; ++e) {
            float s = gb[e];
            for (int c = 0; c < CIN; ++c) s += g_pooled[b * CIN + c] * gw[e * CIN + c];
            lg[e] = s;
        }
        float m = fmaxf(fmaxf(lg[0], lg[1]), fmaxf(lg[2], lg[3]));
        float p[4];
        float Z = 0.f;
        for (int e = 0; e < 4; ++e) { p[e] = expf(lg[e] - m); Z += p[e]; }
        for (int e = 0; e < 4; ++e) p[e] /= Z;
        int i0 = 0;
        for (int e = 1; e < 4; ++e) if (p[e] > p[i0]) i0 = e;   // strict >, lower idx wins ties
        int i1 = -1;
        for (int e = 0; e < 4; ++e) {
            if (e == i0) continue;
            if (i1 < 0 || p[e] > p[i1]) i1 = e;
        }
        float den = p[i0] + p[i1] + 1e-8f;
        g_selidx[b * 2 + 0] = i0; g_selwt[b * 2 + 0] = p[i0] / den;
        g_selidx[b * 2 + 1] = i1; g_selwt[b * 2 + 1] = p[i1] / den;
        s_idx[b * 2 + 0] = i0;
        s_idx[b * 2 + 1] = i1;
    }
    __syncthreads();
    if (t == 0) {
        // stable counting sort, heaviest expert (largest K) first
        int n = 0;
        for (int e = 3; e >= 0; --e)
            for (int z = 0; z < NB * 2; ++z)
                if (s_idx[z] == e) g_sched[n++] = z;
    }
}

// ---------------- launch #4: merged expert conv + BN + GELU, packed f32x2 FMA ---
// OCCUPANCY-2 LAYOUT: 256 threads = 32(ow) x 2(cout-half) x 4(oh-quad).
// Each thread: 32 couts (16 f32x2 pairs) x 2 oh-rows => 32 u64 accumulators
// (64 regs), total regs <= 128 so TWO blocks co-reside per SM (16 warps)
// to hide LDS/LDG latency. Each weight LDS.128 feeds 4 FFMA2.
template <int E, int K, int D, int CHUNK, int WOFF>
__device__ __forceinline__ void conv_body(const float* __restrict__ xb,
                                          float* __restrict__ out,
                                          int z, int tid, float4* sw4) {
    const int pad = D * (K - 1) / 2;
    const int owl = tid & 31;
    const int ch  = (tid >> 5) & 1;
    const int ohq = tid >> 6;
    const int ow  = blockIdx.x * 32 + owl;
    const int oh0 = blockIdx.y * 8 + ohq * 2;     // 2 rows per thread
    const int ows = 2 * ow - pad;

    int ohs[2];
    unsigned rmask[2];
#pragma unroll
    for (int p = 0; p < 2; ++p) {
        ohs[p] = 2 * (oh0 + p) - pad;
        unsigned m = 0;
#pragma unroll
        for (int k = 0; k < K; ++k)
            if ((unsigned)(ohs[p] + D * k) < (unsigned)HW) m |= 1u << k;
        rmask[p] = m;
    }
    unsigned cmask = 0;
#pragma unroll
    for (int k = 0; k < K; ++k)
        if ((unsigned)(ows + D * k) < (unsigned)HW) cmask |= 1u << k;

    unsigned long long acc[2][16];
#pragma unroll
    for (int p = 0; p < 2; ++p)
#pragma unroll
        for (int j = 0; j < 16; ++j) acc[p][j] = 0ULL;

    float* sw = (float*)sw4;
    const float4* wsrc = (const float4*)(g_wT + WOFF);

    for (int cc = 0; cc < CIN; cc += CHUNK) {
        __syncthreads();
        for (int i = tid; i < CHUNK * K * K * 16; i += 256)
            sw4[i] = wsrc[cc * (K * K * 16) + i];
        __syncthreads();

#pragma unroll 1
        for (int cl = 0; cl < CHUNK; ++cl) {
            const float* xp = xb + (size_t)(cc + cl) * (HW * HW);
#pragma unroll 1
            for (int kh = 0; kh < K; ++kh) {
                const float* wrow = sw + ((cl * K + kh) * K) * 64 + ch * 32;
                // ---- batched x loads for the whole kh row (high MLP) ----
                float xv[2 * K];
#pragma unroll
                for (int p = 0; p < 2; ++p) {
                    const float* xr = xp + (ohs[p] + D * kh) * HW + ows;
                    const bool rv = (rmask[p] >> kh) & 1;
#pragma unroll
                    for (int kw = 0; kw < K; ++kw) {
                        float v = 0.f;
                        if (rv && ((cmask >> kw) & 1)) v = __ldg(xr + D * kw);
                        xv[p * K + kw] = v;
                    }
                }
                // ---- pure LDS + FFMA2 ----
#pragma unroll
                for (int kw = 0; kw < K; ++kw) {
                    unsigned long long x2[2];
#pragma unroll
                    for (int p = 0; p < 2; ++p)
                        asm("mov.b64 %0, {%1, %1};" : "=l"(x2[p])
                            : "r"(__float_as_uint(xv[p * K + kw])));
                    const ulonglong2* wq = (const ulonglong2*)(wrow + kw * 64);
#pragma unroll
                    for (int j = 0; j < 8; ++j) {
                        ulonglong2 wv = wq[j];
#pragma unroll
                        for (int p = 0; p < 2; ++p) {
                            asm("fma.rn.f32x2 %0, %1, %2, %0;"
                                : "+l"(acc[p][2 * j + 0]) : "l"(x2[p]), "l"(wv.x));
                            asm("fma.rn.f32x2 %0, %1, %2, %0;"
                                : "+l"(acc[p][2 * j + 1]) : "l"(x2[p]), "l"(wv.y));
                        }
                    }
                }
            }
        }
    }

    // epilogue: BN fold + exact GELU + gate weight; stores coalesced along ow
    const float wt = g_selwt[z];
    const int b = z >> 1, s = z & 1;
#pragma unroll
    for (int p = 0; p < 2; ++p) {
        float* ob = out + ((size_t)b * 128 + s * 64 + ch * 32) * (HO * HO)
                  + (oh0 + p) * HO + ow;
#pragma unroll
        for (int j = 0; j < 16; ++j) {
            unsigned u0, u1;
            asm("mov.b64 {%0, %1}, %2;" : "=r"(u0), "=r"(u1) : "l"(acc[p][j]));
            float v0 = __uint_as_float(u0);
            float v1 = __uint_as_float(u1);
            const int c0 = ch * 32 + 2 * j, c1 = c0 + 1;
            float y0 = v0 * g_bnA[E * 64 + c0] + g_bnB[E * 64 + c0];
            float y1 = v1 * g_bnA[E * 64 + c1] + g_bnB[E * 64 + c1];
            y0 = 0.5f * y0 * (1.f + erff(y0 * 0.70710678118654752f));
            y1 = 0.5f * y1 * (1.f + erff(y1 * 0.70710678118654752f));
            ob[(size_t)(2 * j) * (HO * HO)]     = y0 * wt;
            ob[(size_t)(2 * j + 1) * (HO * HO)] = y1 * wt;
        }
    }
}

__global__ void __launch_bounds__(256, 2)
conv_all_kernel(const float* __restrict__ x, float* __restrict__ out) {
    __shared__ float4 sw4[2592];   // max: E3 CHUNK=2 -> 2*81*64 floats = 41472 B
    const int z = g_sched[blockIdx.z];          // heavy-first schedule
    const int tid = threadIdx.x;
    const float* xb = x + (size_t)(z >> 1) * CIN * HW * HW;
    const int e = g_selidx[z];
    if (e == 0)      conv_body<0, 3, 1, 16, 0     >(xb, out, z, tid, sw4);
    else if (e == 1) conv_body<1, 5, 2, 4,  36864 >(xb, out, z, tid, sw4);
    else if (e == 2) conv_body<2, 7, 3, 2,  139264>(xb, out, z, tid, sw4);
    else             conv_body<3, 9, 4, 2,  339968>(xb, out, z, tid, sw4);
}

// ---------------- launch: exactly 4 launches, conv is #4 (ncu capture slot) -----
extern "C" void kernel_launch(void* const* d_in, const int* in_sizes, int n_in,
                              void* d_out, int out_size) {
    (void)in_sizes; (void)n_in; (void)out_size;
    const float* x   = (const float*)d_in[0];
    const float* w0  = (const float*)d_in[1];
    const float* b0  = (const float*)d_in[2];
    const float* w1  = (const float*)d_in[3];
    const float* b1  = (const float*)d_in[4];
    const float* w2  = (const float*)d_in[5];
    const float* b2  = (const float*)d_in[6];
    const float* w3  = (const float*)d_in[7];
    const float* b3  = (const float*)d_in[8];
    const float* bns = (const float*)d_in[9];
    const float* bnb = (const float*)d_in[10];
    const float* bnm = (const float*)d_in[11];
    const float* bnv = (const float*)d_in[12];
    const float* gw  = (const float*)d_in[13];
    const float* gb  = (const float*)d_in[14];
    float* out = (float*)d_out;

    pool_kernel<<<NB * CIN, 256>>>(x);                               // #1
    twk_all_kernel<<<(671744 + 255) / 256, 256>>>(w0, w1, w2, w3);   // #2
    gatebn_kernel<<<1, 256>>>(gw, gb, bns, bnb, bnm, bnv,
                              b0, b1, b2, b3);                       // #3
    dim3 grid(4, 16, NB * 2);  // 128/32 ow-tiles x 128/8 oh-tiles x (b,slot)
    conv_all_kernel<<<grid, 256>>>(x, out);                          // #4
}